// round 12
// baseline (speedup 1.0000x reference)
#include <cuda_runtime.h>
#include <cstdint>
#include <math.h>

#define NN 4096
#define BB 2
#define TT 25
#define OFFCAP 4096
#define RR2 1089
#define EH 4032

typedef unsigned long long u64;
typedef unsigned short u16;

// ---- device scratch ----
__device__ float g_f[BB][NN];
__device__ float g_land[BB][50];
__device__ int g_arrive;    // monotonically increasing arrival counter (parity-based)

// ============================================================
// Compile-time offsets table: all (di,dj) with di^2+dj^2 <= 1089,
// sorted by (r^2, then lexicographic (di,dj)).
// ============================================================
struct OffTab {
    unsigned short p[OFFCAP];   // (di+33)<<7 | (dj+33); pad 0xFFFF
    float d2[OFFCAP];           // r^2 * (224/63)^2 ; pad 0
};

constexpr OffTab make_offtab() {
    OffTab t{};
    for (int i = 0; i < OFFCAP; ++i) { t.p[i] = 0xFFFF; t.d2[i] = 0.0f; }
    int hist[RR2 + 1] = {};
    for (int a = -33; a <= 33; ++a)
        for (int b = -33; b <= 33; ++b) {
            int r2 = a * a + b * b;
            if (r2 <= RR2) hist[r2]++;
        }
    int pos[RR2 + 1] = {};
    int run = 0;
    for (int r2 = 0; r2 <= RR2; ++r2) { pos[r2] = run; run += hist[r2]; }
    double s2 = (224.0 / 63.0) * (224.0 / 63.0);
    for (int a = -33; a <= 33; ++a)
        for (int b = -33; b <= 33; ++b) {
            int r2 = a * a + b * b;
            if (r2 > RR2) continue;
            int p = pos[r2]++;
            t.p[p] = (unsigned short)(((a + 33) << 7) | (b + 33));
            t.d2[p] = (float)((double)r2 * s2);
        }
    return t;
}

__constant__ OffTab g_tab = make_offtab();

// ============================================================
// Kernel 1: weighted DTM, early-terminating prefix walk.
// ============================================================
__global__ void k_dtm(const float* __restrict__ w_in) {
    __shared__ float sw[NN];
    __shared__ float s_ws[4];
    __shared__ float s_thr;
    int b = blockIdx.y;
    const float* w = w_in + b * NN;
    for (int i = threadIdx.x; i < NN; i += blockDim.x) sw[i] = w[i];
    __syncthreads();
    float ps = 0.f;
    for (int i = threadIdx.x; i < NN; i += blockDim.x) ps += sw[i];
    for (int o = 16; o; o >>= 1) ps += __shfl_xor_sync(~0u, ps, o);
    if ((threadIdx.x & 31) == 0) s_ws[threadIdx.x >> 5] = ps;
    __syncthreads();
    if (threadIdx.x == 0) s_thr = 0.05f * (((s_ws[0] + s_ws[1]) + s_ws[2]) + s_ws[3]);
    __syncthreads();
    float thr = s_thr;

    int p = blockIdx.x * blockDim.x + threadIdx.x;
    int i1 = (p >> 6) - 33, j1 = (p & 63) - 33;
    float excl = 0.f, acc = 0.f;
    for (int t = 0; t < OFFCAP; t += 8) {
        #pragma unroll
        for (int s = 0; s < 8; ++s) {
            unsigned op = (unsigned)g_tab.p[t + s];
            float d2 = g_tab.d2[t + s];
            int ni = i1 + (int)(op >> 7);
            int nj = j1 + (int)(op & 127u);
            float wv = 0.f;
            if (((ni | nj) & ~63) == 0) wv = sw[(ni << 6) | nj];
            float eff = fmaxf(fminf(thr - excl, wv), 0.f);
            acc = fmaf(eff, d2, acc);
            excl += wv;
        }
        if (excl >= thr) break;
    }
    g_f[b][p] = sqrtf(acc / thr);
}

// in-thread compare-exchange: ascending=true keeps min in x
#define CSWAP(x, y, asc) { if (((x) > (y)) == (asc)) { u64 _t = (x); (x) = (y); (y) = _t; } }

// warp-shuffle bitonic substage: element stride j (4..64), stage k
#define SHFL_STEP(J, K) { \
    int _js = (J) >> 2; \
    _Pragma("unroll") \
    for (int _r = 0; _r < 4; ++_r) { \
        u64 _o = __shfl_xor_sync(0xffffffffu, V[_r], _js); \
        int _i = base + _r; \
        bool _keepmin = (((_i & (J)) == 0) == ((_i & (K)) == 0)); \
        V[_r] = _keepmin ? (V[_r] < _o ? V[_r] : _o) : (V[_r] < _o ? _o : V[_r]); \
    } }

// ============================================================
// Kernel 2: persistence (hybrid reg/warp bitonic + watershed +
// sorted edge enumeration + speculative warp UF), landscape, head.
// ============================================================
__global__ void k_ph0(const float* __restrict__ Wg, const float* __restrict__ bg,
                      const float* __restrict__ Wfc, const float* __restrict__ bfc,
                      float* __restrict__ out) {
    extern __shared__ char sm[];
    u64* skey   = (u64*)sm;                 // 32768 (fbits<<12 | v, sorted)
    u16* rank16 = (u16*)(sm + 32768);       // 8192
    u16* ptrA   = (u16*)(sm + 40960);       // 8192
    u16* ptrB   = (u16*)(sm + 49152);       // 8192
    u16* bR     = (u16*)(sm + 57344);       // 8192 basin rank per vertex
    u16* par    = (u16*)(sm + 65536);       // 8192 UF over rank space
    u64* erec   = (u64*)(sm + 73728);       // 65536 boundary edges (wr<<24|ra<<12|rb)
    float* s_b  = (float*)(sm + 139264);    // 8192 (<=2048 bars)
    float* s_d  = (float*)(sm + 147456);    // 8192
    __shared__ int s_nb, s_cnt, s_m, s_last;
    __shared__ int warpAux[64];
    __shared__ float s_land[BB][50];
    __shared__ float s_x[BB][50];
    int b = blockIdx.x, tid = threadIdx.x;
    int warp = tid >> 5, lane = tid & 31;

    // 1.+2. hybrid bitonic sort of (fbits<<12 | v) keys.
    // Thread owns elements [4*tid, 4*tid+4); warp owns a 128-chunk.
    {
        u64 V[4];
        int base = tid << 2;
        #pragma unroll
        for (int r = 0; r < 4; ++r) {
            int i = base + r;
            unsigned fb = __float_as_uint(g_f[b][i]);   // f>=0 -> order-preserving
            V[r] = ((u64)fb << 12) | (unsigned)i;
        }
        if (tid == 0) s_nb = 0;

        // --- phase A: k = 2..128, all in registers / warp shuffles ---
        // k = 2 (j=1); directions differ between the two in-thread pairs
        { bool u0 = ((base & 2) == 0);        CSWAP(V[0], V[1], u0);
          bool u2 = (((base + 2) & 2) == 0);  CSWAP(V[2], V[3], u2); }
        // k = 4 (j=2,1); direction uniform across the 4 elements
        { bool u = ((base & 4) == 0);
          CSWAP(V[0], V[2], u); CSWAP(V[1], V[3], u);
          CSWAP(V[0], V[1], u); CSWAP(V[2], V[3], u); }
        // k = 8..128
        #pragma unroll
        for (int k = 8; k <= 128; k <<= 1) {
            #pragma unroll
            for (int j = 64; j >= 4; j >>= 1)
                if (j <= (k >> 1)) SHFL_STEP(j, k);
            bool u = ((base & k) == 0);
            CSWAP(V[0], V[2], u); CSWAP(V[1], V[3], u);
            CSWAP(V[0], V[1], u); CSWAP(V[2], V[3], u);
        }

        // --- phase B: k = 256..4096; j>=128 via smem, j<=64 in registers ---
        #pragma unroll
        for (int r = 0; r < 4; ++r) skey[base + r] = V[r];
        __syncthreads();
        #pragma unroll
        for (int k = 256; k <= 4096; k <<= 1) {
            for (int j = k >> 1; j >= 128; j >>= 1) {
                #pragma unroll
                for (int p = 0; p < 2; ++p) {
                    int pi = tid + p * 1024;
                    int i = ((pi & ~(j - 1)) << 1) | (pi & (j - 1));
                    int ix = i | j;
                    u64 a = skey[i], c = skey[ix];
                    if ((a > c) == ((i & k) == 0)) { skey[i] = c; skey[ix] = a; }
                }
                __syncthreads();
            }
            #pragma unroll
            for (int r = 0; r < 4; ++r) V[r] = skey[base + r];
            #pragma unroll
            for (int j = 64; j >= 4; j >>= 1) SHFL_STEP(j, k);
            { bool u = ((base & k) == 0);
              CSWAP(V[0], V[2], u); CSWAP(V[1], V[3], u);
              CSWAP(V[0], V[1], u); CSWAP(V[2], V[3], u); }
            #pragma unroll
            for (int r = 0; r < 4; ++r) skey[base + r] = V[r];
            __syncthreads();
        }
    }

    // 3. rank
    for (int r = tid; r < NN; r += 1024) rank16[(int)(skey[r] & 4095ULL)] = (u16)r;
    __syncthreads();

    // 4. steepest descent by rank
    for (int v = tid; v < NN; v += 1024) {
        int i = v >> 6, j = v & 63;
        int best = rank16[v], bv = v;
        if (j > 0)  { int u = v - 1;  int r = rank16[u]; if (r < best) { best = r; bv = u; } }
        if (j < 63) { int u = v + 1;  int r = rank16[u]; if (r < best) { best = r; bv = u; } }
        if (i > 0)  { int u = v - 64; int r = rank16[u]; if (r < best) { best = r; bv = u; } }
        if (i < 63) { int u = v + 64; int r = rank16[u]; if (r < best) { best = r; bv = u; } }
        ptrA[v] = (u16)bv;
    }
    __syncthreads();

    // 5. pointer jumping: A^(4^6) covers any descent path
    for (int rd = 0; rd < 6; ++rd) {
        for (int v = tid; v < NN; v += 1024) ptrB[v] = ptrA[ptrA[v]];
        __syncthreads();
        for (int v = tid; v < NN; v += 1024) ptrA[v] = ptrB[ptrB[v]];
        __syncthreads();
    }

    // 6. basin ranks, basin count, UF init
    {
        int nbloc = 0;
        for (int v = tid; v < NN; v += 1024) {
            int bs = ptrA[v];
            bR[v] = rank16[bs];
            if (bs == v) nbloc++;
        }
        for (int r = tid; r < NN; r += 1024) par[r] = (u16)r;
        for (int o = 16; o; o >>= 1) nbloc += __shfl_xor_sync(~0u, nbloc, o);
        if ((tid & 31) == 0) atomicAdd(&s_nb, nbloc);
    }
    __syncthreads();

    // 7. boundary edges, SORTED BY CONSTRUCTION (rank asc; fixed dir order).
    //    Record = wr<<24 | bR[u]<<12 | bR[v].
    {
        int base_r = tid << 2;
        int c[4], mysum = 0;
        #pragma unroll
        for (int q = 0; q < 4; ++q) {
            int r = base_r + q;
            int v = (int)(skey[r] & 4095ULL);
            int i = v >> 6, j2 = v & 63;
            int bv = bR[v];
            int cc = 0;
            if (j2 > 0)  { int u = v - 1;  if (rank16[u] < r && bR[u] != bv) cc++; }
            if (j2 < 63) { int u = v + 1;  if (rank16[u] < r && bR[u] != bv) cc++; }
            if (i > 0)   { int u = v - 64; if (rank16[u] < r && bR[u] != bv) cc++; }
            if (i < 63)  { int u = v + 64; if (rank16[u] < r && bR[u] != bv) cc++; }
            c[q] = cc; mysum += cc;
        }
        // 3-level exclusive scan
        int pre = mysum;
        for (int o = 1; o < 32; o <<= 1) {
            int t2 = __shfl_up_sync(~0u, pre, o);
            if (lane >= o) pre += t2;
        }
        if (lane == 31) warpAux[warp] = pre;
        pre -= mysum;
        __syncthreads();
        if (warp == 0) {
            int v2 = warpAux[lane];
            int p2 = v2;
            for (int o = 1; o < 32; o <<= 1) {
                int t3 = __shfl_up_sync(~0u, p2, o);
                if (lane >= o) p2 += t3;
            }
            warpAux[32 + lane] = p2 - v2;
            if (lane == 31) s_m = p2;
        }
        __syncthreads();
        int off = warpAux[32 + warp] + pre;
        #pragma unroll
        for (int q = 0; q < 4; ++q) {
            int r = base_r + q;
            if (!c[q]) continue;
            int v = (int)(skey[r] & 4095ULL);
            int i = v >> 6, j2 = v & 63;
            u64 hi = ((u64)r << 24);
            u64 bv = (u64)bR[v];
            if (j2 > 0)  { int u = v - 1;  if (rank16[u] < r && bR[u] != (int)bv) erec[off++] = hi | ((u64)bR[u] << 12) | bv; }
            if (j2 < 63) { int u = v + 1;  if (rank16[u] < r && bR[u] != (int)bv) erec[off++] = hi | ((u64)bR[u] << 12) | bv; }
            if (i > 0)   { int u = v - 64; if (rank16[u] < r && bR[u] != (int)bv) erec[off++] = hi | ((u64)bR[u] << 12) | bv; }
            if (i < 63)  { int u = v + 64; if (rank16[u] < r && bR[u] != (int)bv) erec[off++] = hi | ((u64)bR[u] << 12) | bv; }
        }
    }
    __syncthreads();

    // 8. speculative warp-parallel Kruskal (warp 0); elder = min rank
    if (tid < 32) {
        int nb = s_nb, m = s_m, cnt = 0;
        for (int base = 0; base < m && cnt < nb - 1; base += 32) {
            int idx = base + lane;
            bool ok = idx < m;
            u64 rec = ok ? erec[idx] : 0;
            int wr = (int)(rec >> 24);
            int ra = -1, rb = -1;
            if (ok) {
                ra = (int)((rec >> 12) & 4095ULL);
                rb = (int)(rec & 4095ULL);
                for (;;) {
                    int p1 = par[ra];
                    if (p1 == ra) break;
                    int gp = par[p1];
                    if (gp == p1) { ra = p1; break; }
                    par[ra] = (u16)gp; ra = gp;
                }
                for (;;) {
                    int p1 = par[rb];
                    if (p1 == rb) break;
                    int gp = par[p1];
                    if (gp == p1) { rb = p1; break; }
                    par[rb] = (u16)gp; rb = gp;
                }
            }
            __syncwarp();
            unsigned todo = __ballot_sync(0xffffffffu, ok && (ra != rb));
            while (todo) {
                int l = __ffs(todo) - 1; todo &= todo - 1;
                int ra_l = __shfl_sync(0xffffffffu, ra, l);
                int rb_l = __shfl_sync(0xffffffffu, rb, l);
                if (ra_l != rb_l) {
                    int eld = ra_l < rb_l ? ra_l : rb_l;
                    int yng = ra_l < rb_l ? rb_l : ra_l;
                    if (lane == l) {
                        par[yng] = (u16)eld;
                        s_b[cnt] = __uint_as_float((unsigned)(skey[yng] >> 12));
                        s_d[cnt] = __uint_as_float((unsigned)(skey[wr] >> 12));
                    }
                    cnt++;
                    if (ra == yng) ra = eld;   // in-register staleness repair
                    if (rb == yng) rb = eld;
                }
            }
            __syncwarp();
        }
        if (lane == 0) {   // global bar (f.min, f.max)
            s_b[cnt] = __uint_as_float((unsigned)(skey[0] >> 12));
            s_d[cnt] = __uint_as_float((unsigned)(skey[NN - 1] >> 12));
            s_cnt = cnt;
        }
    }
    __syncthreads();

    // 9. landscape: warp w -> t index w
    int cnt = s_cnt;
    if (warp < TT) {
        float tv = 1.875f * (float)warp;    // linspace(0,45,25) exact
        float m1 = 0.f, m2 = 0.f;           // zero bars contribute 0
        for (int i = lane; i <= cnt; i += 32) {
            float bi = s_b[i], di = s_d[i];
            float tri = fminf(tv - bi, di - tv);
            tri = fmaxf(tri, 0.f);
            if (tri > m1)      { m2 = m1; m1 = tri; }
            else if (tri > m2) { m2 = tri; }
        }
        for (int o = 16; o; o >>= 1) {
            float o1 = __shfl_xor_sync(~0u, m1, o);
            float o2 = __shfl_xor_sync(~0u, m2, o);
            float n1 = fmaxf(m1, o1);
            float n2 = fmaxf(fminf(m1, o1), fmaxf(m2, o2));
            m1 = n1; m2 = n2;
        }
        if (lane == 0) { g_land[b][warp] = m1; g_land[b][TT + warp] = m2; }
    }
    __syncthreads();

    // 10. last block runs the MLP head (parity arrival counter).
    __threadfence();
    if (tid == 0) s_last = ((atomicAdd(&g_arrive, 1) & 1) == 1) ? 1 : 0;
    __syncthreads();
    if (s_last) {
        float* wbuf = (float*)erec;   // reuse: 3000 floats
        for (int i = tid; i < 2500; i += 1024) wbuf[i] = Wg[i];
        for (int i = tid; i < 500; i += 1024) wbuf[2500 + i] = Wfc[i];
        if (tid < BB * 50) {
            int bb = tid / 50, o = tid - bb * 50;
            s_land[bb][o] = g_land[bb][o];
        }
        __syncthreads();
        if (tid < BB * 50) {
            int bb = tid / 50, o = tid - bb * 50;
            float s = bg[o];
            #pragma unroll 10
            for (int i = 0; i < 50; ++i) s += s_land[bb][i] * wbuf[o * 50 + i];
            s_x[bb][o] = s;
        }
        __syncthreads();
        if (tid < 50) out[20 + tid] = fabsf(s_x[0][tid]) + fabsf(s_x[1][tid]);
        if (tid < BB * 10) {
            int bb = tid / 10, j = tid - bb * 10;
            float s = bfc[j];
            #pragma unroll 10
            for (int o = 0; o < 50; ++o) s += fmaxf(s_x[bb][o], 0.f) * wbuf[2500 + j * 50 + o];
            out[bb * 10 + j] = s;
        }
    }
}

// ============================================================
extern "C" void kernel_launch(void* const* d_in, const int* in_sizes, int n_in,
                              void* d_out, int out_size) {
    const float* input = (const float*)d_in[0];   // [2,1,64,64]
    const float* Wg    = (const float*)d_in[1];   // [50,50]
    const float* bg    = (const float*)d_in[2];   // [50]
    const float* Wfc   = (const float*)d_in[3];   // [10,50]
    const float* bfc   = (const float*)d_in[4];   // [10]
    float* out = (float*)d_out;

    cudaFuncSetAttribute(k_ph0, cudaFuncAttributeMaxDynamicSharedMemorySize, 155648);

    dim3 g(NN / 128, BB);
    k_dtm<<<g, 128>>>(input);
    k_ph0<<<BB, 1024, 155648>>>(Wg, bg, Wfc, bfc, out);
}

// round 13
// speedup vs baseline: 1.5418x; 1.5418x over previous
#include <cuda_runtime.h>
#include <cstdint>
#include <math.h>

#define NN 4096
#define BB 2
#define TT 25
#define OFFCAP 4096
#define RR2 1089
#define EH 4032

typedef unsigned long long u64;
typedef unsigned short u16;

// ---- device scratch ----
__device__ float g_f[BB][NN];
__device__ float g_land[BB][50];
__device__ int g_arrive;    // monotonically increasing arrival counter (parity-based)

// ============================================================
// Compile-time offsets table: all (di,dj) with di^2+dj^2 <= 1089,
// sorted by (r^2, then lexicographic (di,dj)).
// ============================================================
struct OffTab {
    unsigned short p[OFFCAP];   // (di+33)<<7 | (dj+33); pad 0xFFFF
    float d2[OFFCAP];           // r^2 * (224/63)^2 ; pad 0
};

constexpr OffTab make_offtab() {
    OffTab t{};
    for (int i = 0; i < OFFCAP; ++i) { t.p[i] = 0xFFFF; t.d2[i] = 0.0f; }
    int hist[RR2 + 1] = {};
    for (int a = -33; a <= 33; ++a)
        for (int b = -33; b <= 33; ++b) {
            int r2 = a * a + b * b;
            if (r2 <= RR2) hist[r2]++;
        }
    int pos[RR2 + 1] = {};
    int run = 0;
    for (int r2 = 0; r2 <= RR2; ++r2) { pos[r2] = run; run += hist[r2]; }
    double s2 = (224.0 / 63.0) * (224.0 / 63.0);
    for (int a = -33; a <= 33; ++a)
        for (int b = -33; b <= 33; ++b) {
            int r2 = a * a + b * b;
            if (r2 > RR2) continue;
            int p = pos[r2]++;
            t.p[p] = (unsigned short)(((a + 33) << 7) | (b + 33));
            t.d2[p] = (float)((double)r2 * s2);
        }
    return t;
}

__constant__ OffTab g_tab = make_offtab();

// ============================================================
// Kernel 1: weighted DTM, early-terminating prefix walk.
// ============================================================
__global__ void k_dtm(const float* __restrict__ w_in) {
    __shared__ float sw[NN];
    __shared__ float s_ws[4];
    __shared__ float s_thr;
    int b = blockIdx.y;
    const float* w = w_in + b * NN;
    for (int i = threadIdx.x; i < NN; i += blockDim.x) sw[i] = w[i];
    __syncthreads();
    float ps = 0.f;
    for (int i = threadIdx.x; i < NN; i += blockDim.x) ps += sw[i];
    for (int o = 16; o; o >>= 1) ps += __shfl_xor_sync(~0u, ps, o);
    if ((threadIdx.x & 31) == 0) s_ws[threadIdx.x >> 5] = ps;
    __syncthreads();
    if (threadIdx.x == 0) s_thr = 0.05f * (((s_ws[0] + s_ws[1]) + s_ws[2]) + s_ws[3]);
    __syncthreads();
    float thr = s_thr;

    int p = blockIdx.x * blockDim.x + threadIdx.x;
    int i1 = (p >> 6) - 33, j1 = (p & 63) - 33;
    float excl = 0.f, acc = 0.f;
    for (int t = 0; t < OFFCAP; t += 8) {
        #pragma unroll
        for (int s = 0; s < 8; ++s) {
            unsigned op = (unsigned)g_tab.p[t + s];
            float d2 = g_tab.d2[t + s];
            int ni = i1 + (int)(op >> 7);
            int nj = j1 + (int)(op & 127u);
            float wv = 0.f;
            if (((ni | nj) & ~63) == 0) wv = sw[(ni << 6) | nj];
            float eff = fmaxf(fminf(thr - excl, wv), 0.f);
            acc = fmaf(eff, d2, acc);
            excl += wv;
        }
        if (excl >= thr) break;
    }
    g_f[b][p] = sqrtf(acc / thr);
}

// in-thread compare-exchange: ascending=true keeps min in x
#define CSWAP(x, y, asc) { if (((x) > (y)) == (asc)) { u64 _t = (x); (x) = (y); (y) = _t; } }

// local bitonic-merge of an aligned 8-chunk, uniform direction u (j=4,2,1)
#define LOCAL_MERGE8(u) { \
    CSWAP(V[0],V[4],u); CSWAP(V[1],V[5],u); CSWAP(V[2],V[6],u); CSWAP(V[3],V[7],u); \
    CSWAP(V[0],V[2],u); CSWAP(V[1],V[3],u); CSWAP(V[4],V[6],u); CSWAP(V[5],V[7],u); \
    CSWAP(V[0],V[1],u); CSWAP(V[2],V[3],u); CSWAP(V[4],V[5],u); CSWAP(V[6],V[7],u); }

// ============================================================
// Kernel 2: persistence (register-merged bitonic + watershed +
// sorted edge enumeration + speculative warp UF), landscape, head.
// ============================================================
__global__ void k_ph0(const float* __restrict__ Wg, const float* __restrict__ bg,
                      const float* __restrict__ Wfc, const float* __restrict__ bfc,
                      float* __restrict__ out) {
    extern __shared__ char sm[];
    u64* skey   = (u64*)sm;                 // 32768 (fbits<<12 | v, sorted)
    u16* rank16 = (u16*)(sm + 32768);       // 8192
    u16* ptrA   = (u16*)(sm + 40960);       // 8192
    u16* ptrB   = (u16*)(sm + 49152);       // 8192
    u16* bR     = (u16*)(sm + 57344);       // 8192 basin rank per vertex
    u16* par    = (u16*)(sm + 65536);       // 8192 UF over rank space
    u64* erec   = (u64*)(sm + 73728);       // 65536 boundary edges (wr<<24|ra<<12|rb)
    float* s_b  = (float*)(sm + 139264);    // 8192 (<=2048 bars)
    float* s_d  = (float*)(sm + 147456);    // 8192
    __shared__ int s_nb, s_cnt, s_m, s_last;
    __shared__ int warpAux[64];
    __shared__ float s_land[BB][50];
    __shared__ float s_x[BB][50];
    int b = blockIdx.x, tid = threadIdx.x;
    int warp = tid >> 5, lane = tid & 31;

    // 1.+2. bitonic sort of (fbits<<12 | v) keys.
    // Stages k<=8 and each stage's j<=4 tail run in registers
    // (512 threads x 8-element aligned chunks, zero shuffles);
    // substages j>=8 use the pair-indexed smem path.
    {
        if (tid == 0) s_nb = 0;
        if (tid < 512) {
            u64 V[8];
            int base = tid << 3;
            #pragma unroll
            for (int r = 0; r < 8; ++r) {
                int i = base + r;
                unsigned fb = __float_as_uint(g_f[b][i]);   // f>=0 -> order-preserving
                V[r] = ((u64)fb << 12) | (unsigned)i;
            }
            // k = 2 (j=1); direction per pair
            #pragma unroll
            for (int m = 0; m < 8; m += 2) {
                bool u = (((base + m) & 2) == 0);
                CSWAP(V[m], V[m + 1], u);
            }
            // k = 4 (j=2,1); direction per 4-half
            #pragma unroll
            for (int h = 0; h < 8; h += 4) {
                bool u = (((base + h) & 4) == 0);
                CSWAP(V[h], V[h + 2], u); CSWAP(V[h + 1], V[h + 3], u);
                CSWAP(V[h], V[h + 1], u); CSWAP(V[h + 2], V[h + 3], u);
            }
            // k = 8 (j=4,2,1); uniform direction within chunk
            { bool u = ((base & 8) == 0); LOCAL_MERGE8(u); }
            #pragma unroll
            for (int r = 0; r < 8; ++r) skey[base + r] = V[r];
        }
        __syncthreads();

        #pragma unroll
        for (int k = 16; k <= 4096; k <<= 1) {
            for (int j = k >> 1; j >= 8; j >>= 1) {
                #pragma unroll
                for (int p = 0; p < 2; ++p) {
                    int pi = tid + p * 1024;
                    int i = ((pi & ~(j - 1)) << 1) | (pi & (j - 1));
                    int ix = i | j;
                    u64 a = skey[i], c = skey[ix];
                    if ((a > c) == ((i & k) == 0)) { skey[i] = c; skey[ix] = a; }
                }
                __syncthreads();
            }
            if (tid < 512) {
                u64 V[8];
                int base = tid << 3;
                #pragma unroll
                for (int r = 0; r < 8; ++r) V[r] = skey[base + r];
                bool u = ((base & k) == 0);
                LOCAL_MERGE8(u);
                #pragma unroll
                for (int r = 0; r < 8; ++r) skey[base + r] = V[r];
            }
            __syncthreads();
        }
    }

    // 3. rank
    for (int r = tid; r < NN; r += 1024) rank16[(int)(skey[r] & 4095ULL)] = (u16)r;
    __syncthreads();

    // 4. steepest descent by rank
    for (int v = tid; v < NN; v += 1024) {
        int i = v >> 6, j = v & 63;
        int best = rank16[v], bv = v;
        if (j > 0)  { int u = v - 1;  int r = rank16[u]; if (r < best) { best = r; bv = u; } }
        if (j < 63) { int u = v + 1;  int r = rank16[u]; if (r < best) { best = r; bv = u; } }
        if (i > 0)  { int u = v - 64; int r = rank16[u]; if (r < best) { best = r; bv = u; } }
        if (i < 63) { int u = v + 64; int r = rank16[u]; if (r < best) { best = r; bv = u; } }
        ptrA[v] = (u16)bv;
    }
    __syncthreads();

    // 5. pointer jumping: A^(4^6) covers any descent path
    for (int rd = 0; rd < 6; ++rd) {
        for (int v = tid; v < NN; v += 1024) ptrB[v] = ptrA[ptrA[v]];
        __syncthreads();
        for (int v = tid; v < NN; v += 1024) ptrA[v] = ptrB[ptrB[v]];
        __syncthreads();
    }

    // 6. basin ranks, basin count, UF init
    {
        int nbloc = 0;
        for (int v = tid; v < NN; v += 1024) {
            int bs = ptrA[v];
            bR[v] = rank16[bs];
            if (bs == v) nbloc++;
        }
        for (int r = tid; r < NN; r += 1024) par[r] = (u16)r;
        for (int o = 16; o; o >>= 1) nbloc += __shfl_xor_sync(~0u, nbloc, o);
        if ((tid & 31) == 0) atomicAdd(&s_nb, nbloc);
    }
    __syncthreads();

    // 7. boundary edges, SORTED BY CONSTRUCTION (rank asc; fixed dir order).
    //    Record = wr<<24 | bR[u]<<12 | bR[v].
    {
        int base_r = tid << 2;
        int c[4], mysum = 0;
        #pragma unroll
        for (int q = 0; q < 4; ++q) {
            int r = base_r + q;
            int v = (int)(skey[r] & 4095ULL);
            int i = v >> 6, j2 = v & 63;
            int bv = bR[v];
            int cc = 0;
            if (j2 > 0)  { int u = v - 1;  if (rank16[u] < r && bR[u] != bv) cc++; }
            if (j2 < 63) { int u = v + 1;  if (rank16[u] < r && bR[u] != bv) cc++; }
            if (i > 0)   { int u = v - 64; if (rank16[u] < r && bR[u] != bv) cc++; }
            if (i < 63)  { int u = v + 64; if (rank16[u] < r && bR[u] != bv) cc++; }
            c[q] = cc; mysum += cc;
        }
        // 3-level exclusive scan
        int pre = mysum;
        for (int o = 1; o < 32; o <<= 1) {
            int t2 = __shfl_up_sync(~0u, pre, o);
            if (lane >= o) pre += t2;
        }
        if (lane == 31) warpAux[warp] = pre;
        pre -= mysum;
        __syncthreads();
        if (warp == 0) {
            int v2 = warpAux[lane];
            int p2 = v2;
            for (int o = 1; o < 32; o <<= 1) {
                int t3 = __shfl_up_sync(~0u, p2, o);
                if (lane >= o) p2 += t3;
            }
            warpAux[32 + lane] = p2 - v2;
            if (lane == 31) s_m = p2;
        }
        __syncthreads();
        int off = warpAux[32 + warp] + pre;
        #pragma unroll
        for (int q = 0; q < 4; ++q) {
            int r = base_r + q;
            if (!c[q]) continue;
            int v = (int)(skey[r] & 4095ULL);
            int i = v >> 6, j2 = v & 63;
            u64 hi = ((u64)r << 24);
            u64 bv = (u64)bR[v];
            if (j2 > 0)  { int u = v - 1;  if (rank16[u] < r && bR[u] != (int)bv) erec[off++] = hi | ((u64)bR[u] << 12) | bv; }
            if (j2 < 63) { int u = v + 1;  if (rank16[u] < r && bR[u] != (int)bv) erec[off++] = hi | ((u64)bR[u] << 12) | bv; }
            if (i > 0)   { int u = v - 64; if (rank16[u] < r && bR[u] != (int)bv) erec[off++] = hi | ((u64)bR[u] << 12) | bv; }
            if (i < 63)  { int u = v + 64; if (rank16[u] < r && bR[u] != (int)bv) erec[off++] = hi | ((u64)bR[u] << 12) | bv; }
        }
    }
    __syncthreads();

    // 8. speculative warp-parallel Kruskal (warp 0); elder = min rank
    if (tid < 32) {
        int nb = s_nb, m = s_m, cnt = 0;
        for (int base = 0; base < m && cnt < nb - 1; base += 32) {
            int idx = base + lane;
            bool ok = idx < m;
            u64 rec = ok ? erec[idx] : 0;
            int wr = (int)(rec >> 24);
            int ra = -1, rb = -1;
            if (ok) {
                ra = (int)((rec >> 12) & 4095ULL);
                rb = (int)(rec & 4095ULL);
                for (;;) {
                    int p1 = par[ra];
                    if (p1 == ra) break;
                    int gp = par[p1];
                    if (gp == p1) { ra = p1; break; }
                    par[ra] = (u16)gp; ra = gp;
                }
                for (;;) {
                    int p1 = par[rb];
                    if (p1 == rb) break;
                    int gp = par[p1];
                    if (gp == p1) { rb = p1; break; }
                    par[rb] = (u16)gp; rb = gp;
                }
            }
            __syncwarp();
            unsigned todo = __ballot_sync(0xffffffffu, ok && (ra != rb));
            while (todo) {
                int l = __ffs(todo) - 1; todo &= todo - 1;
                int ra_l = __shfl_sync(0xffffffffu, ra, l);
                int rb_l = __shfl_sync(0xffffffffu, rb, l);
                if (ra_l != rb_l) {
                    int eld = ra_l < rb_l ? ra_l : rb_l;
                    int yng = ra_l < rb_l ? rb_l : ra_l;
                    if (lane == l) {
                        par[yng] = (u16)eld;
                        s_b[cnt] = __uint_as_float((unsigned)(skey[yng] >> 12));
                        s_d[cnt] = __uint_as_float((unsigned)(skey[wr] >> 12));
                    }
                    cnt++;
                    if (ra == yng) ra = eld;   // in-register staleness repair
                    if (rb == yng) rb = eld;
                }
            }
            __syncwarp();
        }
        if (lane == 0) {   // global bar (f.min, f.max)
            s_b[cnt] = __uint_as_float((unsigned)(skey[0] >> 12));
            s_d[cnt] = __uint_as_float((unsigned)(skey[NN - 1] >> 12));
            s_cnt = cnt;
        }
    }
    __syncthreads();

    // 9. landscape: warp w -> t index w
    int cnt = s_cnt;
    if (warp < TT) {
        float tv = 1.875f * (float)warp;    // linspace(0,45,25) exact
        float m1 = 0.f, m2 = 0.f;           // zero bars contribute 0
        for (int i = lane; i <= cnt; i += 32) {
            float bi = s_b[i], di = s_d[i];
            float tri = fminf(tv - bi, di - tv);
            tri = fmaxf(tri, 0.f);
            if (tri > m1)      { m2 = m1; m1 = tri; }
            else if (tri > m2) { m2 = tri; }
        }
        for (int o = 16; o; o >>= 1) {
            float o1 = __shfl_xor_sync(~0u, m1, o);
            float o2 = __shfl_xor_sync(~0u, m2, o);
            float n1 = fmaxf(m1, o1);
            float n2 = fmaxf(fminf(m1, o1), fmaxf(m2, o2));
            m1 = n1; m2 = n2;
        }
        if (lane == 0) { g_land[b][warp] = m1; g_land[b][TT + warp] = m2; }
    }
    __syncthreads();

    // 10. last block runs the MLP head (parity arrival counter:
    // each launch adds exactly BB=2 arrivals; odd old-value marks
    // the last block of this launch on every graph replay).
    __threadfence();
    if (tid == 0) s_last = ((atomicAdd(&g_arrive, 1) & 1) == 1) ? 1 : 0;
    __syncthreads();
    if (s_last) {
        float* wbuf = (float*)erec;   // reuse: 3000 floats
        for (int i = tid; i < 2500; i += 1024) wbuf[i] = Wg[i];
        for (int i = tid; i < 500; i += 1024) wbuf[2500 + i] = Wfc[i];
        if (tid < BB * 50) {
            int bb = tid / 50, o = tid - bb * 50;
            s_land[bb][o] = g_land[bb][o];
        }
        __syncthreads();
        if (tid < BB * 50) {
            int bb = tid / 50, o = tid - bb * 50;
            float s = bg[o];
            #pragma unroll 10
            for (int i = 0; i < 50; ++i) s += s_land[bb][i] * wbuf[o * 50 + i];
            s_x[bb][o] = s;
        }
        __syncthreads();
        if (tid < 50) out[20 + tid] = fabsf(s_x[0][tid]) + fabsf(s_x[1][tid]);
        if (tid < BB * 10) {
            int bb = tid / 10, j = tid - bb * 10;
            float s = bfc[j];
            #pragma unroll 10
            for (int o = 0; o < 50; ++o) s += fmaxf(s_x[bb][o], 0.f) * wbuf[2500 + j * 50 + o];
            out[bb * 10 + j] = s;
        }
    }
}

// ============================================================
extern "C" void kernel_launch(void* const* d_in, const int* in_sizes, int n_in,
                              void* d_out, int out_size) {
    const float* input = (const float*)d_in[0];   // [2,1,64,64]
    const float* Wg    = (const float*)d_in[1];   // [50,50]
    const float* bg    = (const float*)d_in[2];   // [50]
    const float* Wfc   = (const float*)d_in[3];   // [10,50]
    const float* bfc   = (const float*)d_in[4];   // [10]
    float* out = (float*)d_out;

    cudaFuncSetAttribute(k_ph0, cudaFuncAttributeMaxDynamicSharedMemorySize, 155648);

    dim3 g(NN / 128, BB);
    k_dtm<<<g, 128>>>(input);
    k_ph0<<<BB, 1024, 155648>>>(Wg, bg, Wfc, bfc, out);
}

// round 16
// speedup vs baseline: 2.2966x; 1.4896x over previous
#include <cuda_runtime.h>
#include <cstdint>
#include <math.h>

#define NN 4096
#define BB 2
#define TT 25
#define OFFCAP 4096
#define RR2 1089
#define EH 4032
#define HASHN 8192
#define HASHMASK 8191
#define EMPTY64 0xFFFFFFFFFFFFFFFFULL

typedef unsigned long long u64;
typedef unsigned short u16;

// ---- device scratch ----
__device__ float g_f[BB][NN];
__device__ float g_land[BB][50];
__device__ int g_arrive;    // monotonically increasing arrival counter (parity-based)

// ============================================================
// Compile-time offsets table: all (di,dj) with di^2+dj^2 <= 1089,
// sorted by (r^2, then lexicographic (di,dj)).
// ============================================================
struct OffTab {
    unsigned short p[OFFCAP];   // (di+33)<<7 | (dj+33); pad 0xFFFF
    float d2[OFFCAP];           // r^2 * (224/63)^2 ; pad 0
};

constexpr OffTab make_offtab() {
    OffTab t{};
    for (int i = 0; i < OFFCAP; ++i) { t.p[i] = 0xFFFF; t.d2[i] = 0.0f; }
    int hist[RR2 + 1] = {};
    for (int a = -33; a <= 33; ++a)
        for (int b = -33; b <= 33; ++b) {
            int r2 = a * a + b * b;
            if (r2 <= RR2) hist[r2]++;
        }
    int pos[RR2 + 1] = {};
    int run = 0;
    for (int r2 = 0; r2 <= RR2; ++r2) { pos[r2] = run; run += hist[r2]; }
    double s2 = (224.0 / 63.0) * (224.0 / 63.0);
    for (int a = -33; a <= 33; ++a)
        for (int b = -33; b <= 33; ++b) {
            int r2 = a * a + b * b;
            if (r2 > RR2) continue;
            int p = pos[r2]++;
            t.p[p] = (unsigned short)(((a + 33) << 7) | (b + 33));
            t.d2[p] = (float)((double)r2 * s2);
        }
    return t;
}

__constant__ OffTab g_tab = make_offtab();

// ============================================================
// Kernel 1: weighted DTM, early-terminating prefix walk.
// ============================================================
__global__ void k_dtm(const float* __restrict__ w_in) {
    __shared__ float sw[NN];
    __shared__ float s_ws[4];
    __shared__ float s_thr;
    int b = blockIdx.y;
    const float* w = w_in + b * NN;
    for (int i = threadIdx.x; i < NN; i += blockDim.x) sw[i] = w[i];
    __syncthreads();
    float ps = 0.f;
    for (int i = threadIdx.x; i < NN; i += blockDim.x) ps += sw[i];
    for (int o = 16; o; o >>= 1) ps += __shfl_xor_sync(~0u, ps, o);
    if ((threadIdx.x & 31) == 0) s_ws[threadIdx.x >> 5] = ps;
    __syncthreads();
    if (threadIdx.x == 0) s_thr = 0.05f * (((s_ws[0] + s_ws[1]) + s_ws[2]) + s_ws[3]);
    __syncthreads();
    float thr = s_thr;

    int p = blockIdx.x * blockDim.x + threadIdx.x;
    int i1 = (p >> 6) - 33, j1 = (p & 63) - 33;
    float excl = 0.f, acc = 0.f;
    for (int t = 0; t < OFFCAP; t += 8) {
        #pragma unroll
        for (int s = 0; s < 8; ++s) {
            unsigned op = (unsigned)g_tab.p[t + s];
            float d2 = g_tab.d2[t + s];
            int ni = i1 + (int)(op >> 7);
            int nj = j1 + (int)(op & 127u);
            float wv = 0.f;
            if (((ni | nj) & ~63) == 0) wv = sw[(ni << 6) | nj];
            float eff = fmaxf(fminf(thr - excl, wv), 0.f);
            acc = fmaf(eff, d2, acc);
            excl += wv;
        }
        if (excl >= thr) break;
    }
    g_f[b][p] = sqrtf(acc / thr);
}

// ============================================================
// Kernel 2: persistence — sortless watershed + hash saddle dedup
// + tiny sorted Kruskal, fused landscape + MLP head.
//
// smem layout (bytes):
//   vkey  u64[4096]   0      .. 32768   (fbits<<12 | v, per-vertex)
//   tabl  u64[8192]   32768  .. 98304   (pair hash; later wbuf)
//   earr  u64[8192]   98304  .. 163840  (dedup'd saddle records)
//   ptrA  u16[4096]   163840 .. 172032
//   ptrB  u16[4096]   172032 .. 180224
//   broot u16[4096]   180224 .. 188416  (basin root vertex)
//   par   u16[4096]   188416 .. 196608  (UF over vertex ids)
//   s_b   f32[2048]   196608 .. 204800
//   s_d   f32[2048]   204800 .. 212992
// ============================================================
__global__ void k_ph0(const float* __restrict__ Wg, const float* __restrict__ bg,
                      const float* __restrict__ Wfc, const float* __restrict__ bfc,
                      float* __restrict__ out) {
    extern __shared__ char sm[];
    u64* vkey  = (u64*)sm;
    u64* tabl  = (u64*)(sm + 32768);
    u64* earr  = (u64*)(sm + 98304);
    u16* ptrA  = (u16*)(sm + 163840);
    u16* ptrB  = (u16*)(sm + 172032);
    u16* broot = (u16*)(sm + 180224);
    u16* par   = (u16*)(sm + 188416);
    float* s_b = (float*)(sm + 196608);
    float* s_d = (float*)(sm + 204800);
    __shared__ int s_nb, s_cnt, s_m, s_last;
    __shared__ u64 s_minkey, s_maxkey;
    __shared__ float s_land[BB][50];
    __shared__ float s_x[BB][50];
    int b = blockIdx.x, tid = threadIdx.x;
    int warp = tid >> 5, lane = tid & 31;

    // A. per-vertex keys (f, index) lexicographic; counter inits
    for (int i = tid; i < NN; i += 1024) {
        unsigned fb = __float_as_uint(g_f[b][i]);   // f>=0 -> order-preserving bits
        vkey[i] = ((u64)fb << 12) | (unsigned)i;
    }
    if (tid == 0) { s_nb = 0; s_m = 0; s_minkey = EMPTY64; s_maxkey = 0ULL; }
    __syncthreads();

    // B. global min/max key + steepest descent (argmin neighbor key)
    {
        u64 mn = EMPTY64, mx = 0ULL;
        for (int v = tid; v < NN; v += 1024) {
            u64 kv = vkey[v];
            mn = mn < kv ? mn : kv;
            mx = mx > kv ? mx : kv;
            int i = v >> 6, j = v & 63;
            u64 bk = kv; int bv = v;
            if (j > 0)  { u64 k = vkey[v - 1];  if (k < bk) { bk = k; bv = v - 1; } }
            if (j < 63) { u64 k = vkey[v + 1];  if (k < bk) { bk = k; bv = v + 1; } }
            if (i > 0)  { u64 k = vkey[v - 64]; if (k < bk) { bk = k; bv = v - 64; } }
            if (i < 63) { u64 k = vkey[v + 64]; if (k < bk) { bk = k; bv = v + 64; } }
            ptrA[v] = (u16)bv;
        }
        for (int o = 16; o; o >>= 1) {
            u64 t1 = __shfl_xor_sync(~0u, mn, o); mn = mn < t1 ? mn : t1;
            u64 t2 = __shfl_xor_sync(~0u, mx, o); mx = mx > t2 ? mx : t2;
        }
        if (lane == 0) {
            atomicMin((unsigned long long*)&s_minkey, mn);
            atomicMax((unsigned long long*)&s_maxkey, mx);
        }
    }
    __syncthreads();

    // C. pointer jumping: A^(4^6) covers any descent path
    for (int rd = 0; rd < 6; ++rd) {
        for (int v = tid; v < NN; v += 1024) ptrB[v] = ptrA[ptrA[v]];
        __syncthreads();
        for (int v = tid; v < NN; v += 1024) ptrA[v] = ptrB[ptrB[v]];
        __syncthreads();
    }

    // D. basin roots, basin count, UF init
    {
        int nbloc = 0;
        for (int v = tid; v < NN; v += 1024) {
            int bs = ptrA[v];
            broot[v] = (u16)bs;
            par[v] = (u16)v;
            if (bs == v) nbloc++;
        }
        for (int o = 16; o; o >>= 1) nbloc += __shfl_xor_sync(~0u, nbloc, o);
        if ((tid & 31) == 0) atomicAdd(&s_nb, nbloc);
    }

    // E. hash table init
    for (int i = tid; i < HASHN; i += 1024) tabl[i] = EMPTY64;
    __syncthreads();

    // F. saddle dedup: per basin pair keep min-weight boundary edge.
    //    record = deathfbits<<24 | a<<12 | c  (a<c basin root vertices)
    for (int e = tid; e < 8064; e += 1024) {
        int u, v;
        if (e < EH) { int r = e / 63, c = e - r * 63; u = (r << 6) + c; v = u + 1; }
        else        { u = e - EH; v = u + 64; }
        int ru = broot[u], rv = broot[v];
        if (ru == rv) continue;
        u64 ku = vkey[u], kv = vkey[v];
        u64 wk = ku > kv ? ku : kv;
        unsigned fb = (unsigned)(wk >> 12);
        int a = ru < rv ? ru : rv;
        int c = ru < rv ? rv : ru;
        unsigned pk = ((unsigned)a << 12) | (unsigned)c;
        u64 rec = ((u64)fb << 24) | pk;
        unsigned slot = (pk * 2654435761u) >> 19;   // 13-bit hash
        for (;;) {
            u64 cur = tabl[slot];
            if (cur == EMPTY64) {
                u64 prev = atomicCAS((unsigned long long*)&tabl[slot], EMPTY64, rec);
                if (prev == EMPTY64) break;
                cur = prev;
            }
            if ((unsigned)(cur & 0xFFFFFFu) == pk) {
                atomicMin((unsigned long long*)&tabl[slot], rec);
                break;
            }
            slot = (slot + 1) & HASHMASK;
        }
    }
    __syncthreads();

    // G. compact table entries into earr
    for (int i = tid; i < HASHN; i += 1024) {
        u64 r = tabl[i];
        if (r != EMPTY64) earr[atomicAdd(&s_m, 1)] = r;
    }
    __syncthreads();
    int m = s_m;
    int P = 32; while (P < m) P <<= 1;
    for (int i = m + tid; i < P; i += 1024) earr[i] = EMPTY64;
    __syncthreads();

    // H. bitonic sort earr[0..P) (unique keys -> deterministic)
    for (int k = 2; k <= P; k <<= 1)
        for (int j = k >> 1; j > 0; j >>= 1) {
            for (int p = tid; p < (P >> 1); p += 1024) {
                int i = ((p & ~(j - 1)) << 1) | (p & (j - 1));
                int ix = i | j;
                u64 a = earr[i], c = earr[ix];
                if ((a > c) == ((i & k) == 0)) { earr[i] = c; earr[ix] = a; }
            }
            __syncthreads();
        }

    // I. warp 0: speculative warp-parallel Kruskal over saddles.
    //    Other warps: preload MLP weights into tabl (free now).
    if (warp == 0) {
        int nb = s_nb, cnt = 0;
        for (int base = 0; base < m && cnt < nb - 1; base += 32) {
            int idx = base + lane;
            bool ok = idx < m;
            u64 rec = ok ? earr[idx] : 0;
            int ra = -1, rb = -1;
            if (ok) {
                ra = (int)((rec >> 12) & 4095ULL);
                rb = (int)(rec & 4095ULL);
                for (;;) {
                    int p1 = par[ra];
                    if (p1 == ra) break;
                    int gp = par[p1];
                    if (gp == p1) { ra = p1; break; }
                    par[ra] = (u16)gp; ra = gp;
                }
                for (;;) {
                    int p1 = par[rb];
                    if (p1 == rb) break;
                    int gp = par[p1];
                    if (gp == p1) { rb = p1; break; }
                    par[rb] = (u16)gp; rb = gp;
                }
            }
            __syncwarp();
            unsigned todo = __ballot_sync(0xffffffffu, ok && (ra != rb));
            while (todo) {
                int l = __ffs(todo) - 1; todo &= todo - 1;
                // ALL lanes participate in every shuffle (convergent code)
                int ra_l = __shfl_sync(0xffffffffu, ra, l);
                int rb_l = __shfl_sync(0xffffffffu, rb, l);
                u64 rec_l = __shfl_sync(0xffffffffu, rec, l);
                if (ra_l != rb_l) {
                    // elder = smaller (f, vid) key — matches reference exactly
                    bool ue = vkey[ra_l] < vkey[rb_l];
                    int eld = ue ? ra_l : rb_l;
                    int yng = ue ? rb_l : ra_l;
                    if (lane == l) {
                        par[yng] = (u16)eld;
                        s_b[cnt] = __uint_as_float((unsigned)(vkey[yng] >> 12));
                        s_d[cnt] = __uint_as_float((unsigned)(rec_l >> 24));
                    }
                    cnt++;
                    if (ra == yng) ra = eld;   // in-register staleness repair
                    if (rb == yng) rb = eld;
                }
            }
            __syncwarp();
        }
        if (lane == 0) {   // appended global bar (f.min, f.max)
            s_b[cnt] = __uint_as_float((unsigned)(s_minkey >> 12));
            s_d[cnt] = __uint_as_float((unsigned)(s_maxkey >> 12));
            s_cnt = cnt;
        }
    } else {
        // overlap: weights into wbuf = tabl region
        float* wbuf = (float*)tabl;
        for (int i = tid - 32; i < 2500; i += 992) wbuf[i] = Wg[i];
        for (int i = tid - 32; i < 500; i += 992) wbuf[2500 + i] = Wfc[i];
    }
    __syncthreads();

    // J. landscape: warp w -> t index w; only cnt+1 bars
    int cnt = s_cnt;
    if (warp < TT) {
        float tv = 1.875f * (float)warp;    // linspace(0,45,25) exact
        float m1 = 0.f, m2 = 0.f;           // zero bars contribute 0
        for (int i = lane; i <= cnt; i += 32) {
            float bi = s_b[i], di = s_d[i];
            float tri = fminf(tv - bi, di - tv);
            tri = fmaxf(tri, 0.f);
            if (tri > m1)      { m2 = m1; m1 = tri; }
            else if (tri > m2) { m2 = tri; }
        }
        for (int o = 16; o; o >>= 1) {
            float o1 = __shfl_xor_sync(~0u, m1, o);
            float o2 = __shfl_xor_sync(~0u, m2, o);
            float n1 = fmaxf(m1, o1);
            float n2 = fmaxf(fminf(m1, o1), fmaxf(m2, o2));
            m1 = n1; m2 = n2;
        }
        if (lane == 0) { g_land[b][warp] = m1; g_land[b][TT + warp] = m2; }
    }
    __syncthreads();

    // K. last block runs the MLP head (parity arrival counter:
    // each launch adds exactly BB=2 arrivals; odd old-value marks
    // the last block of this launch on every graph replay).
    __threadfence();
    if (tid == 0) s_last = ((atomicAdd(&g_arrive, 1) & 1) == 1) ? 1 : 0;
    __syncthreads();
    if (s_last) {
        float* wbuf = (float*)tabl;   // preloaded during phase I
        if (tid < BB * 50) {
            int bb = tid / 50, o = tid - bb * 50;
            s_land[bb][o] = g_land[bb][o];
        }
        __syncthreads();
        if (tid < BB * 50) {
            int bb = tid / 50, o = tid - bb * 50;
            float s = bg[o];
            #pragma unroll 10
            for (int i = 0; i < 50; ++i) s += s_land[bb][i] * wbuf[o * 50 + i];
            s_x[bb][o] = s;
        }
        __syncthreads();
        if (tid < 50) out[20 + tid] = fabsf(s_x[0][tid]) + fabsf(s_x[1][tid]);
        if (tid < BB * 10) {
            int bb = tid / 10, j = tid - bb * 10;
            float s = bfc[j];
            #pragma unroll 10
            for (int o = 0; o < 50; ++o) s += fmaxf(s_x[bb][o], 0.f) * wbuf[2500 + j * 50 + o];
            out[bb * 10 + j] = s;
        }
    }
}

// ============================================================
extern "C" void kernel_launch(void* const* d_in, const int* in_sizes, int n_in,
                              void* d_out, int out_size) {
    const float* input = (const float*)d_in[0];   // [2,1,64,64]
    const float* Wg    = (const float*)d_in[1];   // [50,50]
    const float* bg    = (const float*)d_in[2];   // [50]
    const float* Wfc   = (const float*)d_in[3];   // [10,50]
    const float* bfc   = (const float*)d_in[4];   // [10]
    float* out = (float*)d_out;

    cudaFuncSetAttribute(k_ph0, cudaFuncAttributeMaxDynamicSharedMemorySize, 212992);

    dim3 g(NN / 128, BB);
    k_dtm<<<g, 128>>>(input);
    k_ph0<<<BB, 1024, 212992>>>(Wg, bg, Wfc, bfc, out);
}